// round 1
// baseline (speedup 1.0000x reference)
#include <cuda_runtime.h>

#define BATCH 16
#define CH 3
#define NPIX (1024 * 1024)
#define NVEC (NPIX / 4)
#define NACC 21

// Scratch (allocation-free per harness rules)
__device__ double g_acc[BATCH][NACC];
__device__ float  g_x[BATCH][9];
__device__ float  g_off[BATCH][3];

__global__ void zero_acc_kernel() {
    int i = blockIdx.x * blockDim.x + threadIdx.x;
    if (i < BATCH * NACC) ((double*)g_acc)[i] = 0.0;
}

// Pass 1: raw moments per batch.
// acc layout: [0..2]=sumA, [3..5]=sumB,
// [6..11]=sumAA (00,01,02,11,12,22), [12..20]=sumBA (row-major 3x3: B_i * A_j)
__global__ void __launch_bounds__(256) reduce_kernel(const float* __restrict__ src,
                                                     const float* __restrict__ dst) {
    const int b = blockIdx.y;
    const float4* A0 = (const float4*)(src + (size_t)b * CH * NPIX);
    const float4* A1 = A0 + NVEC;
    const float4* A2 = A1 + NVEC;
    const float4* B0 = (const float4*)(dst + (size_t)b * CH * NPIX);
    const float4* B1 = B0 + NVEC;
    const float4* B2 = B1 + NVEC;

    float acc[NACC];
#pragma unroll
    for (int k = 0; k < NACC; k++) acc[k] = 0.0f;

    const int stride = gridDim.x * blockDim.x;
    for (int i = blockIdx.x * blockDim.x + threadIdx.x; i < NVEC; i += stride) {
        float4 a0 = A0[i], a1 = A1[i], a2 = A2[i];
        float4 b0 = B0[i], b1 = B1[i], b2 = B2[i];
#define LANE(c)                                                                 \
        {                                                                       \
            float x0 = a0.c, x1 = a1.c, x2 = a2.c;                              \
            float y0 = b0.c, y1 = b1.c, y2 = b2.c;                              \
            acc[0] += x0;  acc[1] += x1;  acc[2] += x2;                         \
            acc[3] += y0;  acc[4] += y1;  acc[5] += y2;                         \
            acc[6]  += x0 * x0; acc[7]  += x0 * x1; acc[8]  += x0 * x2;         \
            acc[9]  += x1 * x1; acc[10] += x1 * x2; acc[11] += x2 * x2;         \
            acc[12] += y0 * x0; acc[13] += y0 * x1; acc[14] += y0 * x2;         \
            acc[15] += y1 * x0; acc[16] += y1 * x1; acc[17] += y1 * x2;         \
            acc[18] += y2 * x0; acc[19] += y2 * x1; acc[20] += y2 * x2;         \
        }
        LANE(x) LANE(y) LANE(z) LANE(w)
#undef LANE
    }

    // Block reduction: warp shuffle, then cross-warp via shared.
    __shared__ float s[NACC][8];
    const int lane = threadIdx.x & 31;
    const int warp = threadIdx.x >> 5;
#pragma unroll
    for (int k = 0; k < NACC; k++) {
        float v = acc[k];
#pragma unroll
        for (int o = 16; o > 0; o >>= 1) v += __shfl_down_sync(0xffffffffu, v, o);
        if (lane == 0) s[k][warp] = v;
    }
    __syncthreads();
    if (threadIdx.x < NACC) {
        float v = 0.0f;
#pragma unroll
        for (int w = 0; w < 8; w++) v += s[threadIdx.x][w];
        atomicAdd(&g_acc[b][threadIdx.x], (double)v);
    }
}

// Pass 2: per-batch 3x3 solve in double precision.
__global__ void solve_kernel() {
    int b = threadIdx.x;
    if (b >= BATCH) return;
    const double n = (double)NPIX;
    const double* a = g_acc[b];

    double mA[3] = {a[0] / n, a[1] / n, a[2] / n};
    double mB[3] = {a[3] / n, a[4] / n, a[5] / n};

    double AA[3][3];
    AA[0][0] = a[6]  - n * mA[0] * mA[0] + 0.001;
    AA[0][1] = a[7]  - n * mA[0] * mA[1];
    AA[0][2] = a[8]  - n * mA[0] * mA[2];
    AA[1][1] = a[9]  - n * mA[1] * mA[1] + 0.001;
    AA[1][2] = a[10] - n * mA[1] * mA[2];
    AA[2][2] = a[11] - n * mA[2] * mA[2] + 0.001;
    AA[1][0] = AA[0][1]; AA[2][0] = AA[0][2]; AA[2][1] = AA[1][2];

    double BA[3][3];
#pragma unroll
    for (int i = 0; i < 3; i++)
#pragma unroll
        for (int j = 0; j < 3; j++)
            BA[i][j] = a[12 + 3 * i + j] - n * mB[i] * mA[j];

    // 3x3 inverse via adjugate
    double c00 =  (AA[1][1] * AA[2][2] - AA[1][2] * AA[2][1]);
    double c01 = -(AA[1][0] * AA[2][2] - AA[1][2] * AA[2][0]);
    double c02 =  (AA[1][0] * AA[2][1] - AA[1][1] * AA[2][0]);
    double c10 = -(AA[0][1] * AA[2][2] - AA[0][2] * AA[2][1]);
    double c11 =  (AA[0][0] * AA[2][2] - AA[0][2] * AA[2][0]);
    double c12 = -(AA[0][0] * AA[2][1] - AA[0][1] * AA[2][0]);
    double c20 =  (AA[0][1] * AA[1][2] - AA[0][2] * AA[1][1]);
    double c21 = -(AA[0][0] * AA[1][2] - AA[0][2] * AA[1][0]);
    double c22 =  (AA[0][0] * AA[1][1] - AA[0][1] * AA[1][0]);
    double det = AA[0][0] * c00 + AA[0][1] * c01 + AA[0][2] * c02;
    double id = 1.0 / det;
    double inv[3][3] = {{c00 * id, c10 * id, c20 * id},
                        {c01 * id, c11 * id, c21 * id},
                        {c02 * id, c12 * id, c22 * id}};

    // x = BA @ inv ; off_i = mB_i - sum_j x_ij * mA_j
#pragma unroll
    for (int i = 0; i < 3; i++) {
        double xi[3];
#pragma unroll
        for (int j = 0; j < 3; j++)
            xi[j] = BA[i][0] * inv[0][j] + BA[i][1] * inv[1][j] + BA[i][2] * inv[2][j];
        g_x[b][3 * i + 0] = (float)xi[0];
        g_x[b][3 * i + 1] = (float)xi[1];
        g_x[b][3 * i + 2] = (float)xi[2];
        g_off[b][i] = (float)(mB[i] - (xi[0] * mA[0] + xi[1] * mA[1] + xi[2] * mA[2]));
    }
}

// Pass 3: out_i = sum_j x_ij * A_j + off_i
__global__ void __launch_bounds__(256) apply_kernel(const float* __restrict__ src,
                                                    float* __restrict__ out) {
    const int b = blockIdx.y;
    const float x00 = g_x[b][0], x01 = g_x[b][1], x02 = g_x[b][2];
    const float x10 = g_x[b][3], x11 = g_x[b][4], x12 = g_x[b][5];
    const float x20 = g_x[b][6], x21 = g_x[b][7], x22 = g_x[b][8];
    const float o0 = g_off[b][0], o1 = g_off[b][1], o2 = g_off[b][2];

    const float4* A0 = (const float4*)(src + (size_t)b * CH * NPIX);
    const float4* A1 = A0 + NVEC;
    const float4* A2 = A1 + NVEC;
    float4* O0 = (float4*)(out + (size_t)b * CH * NPIX);
    float4* O1 = O0 + NVEC;
    float4* O2 = O1 + NVEC;

    const int stride = gridDim.x * blockDim.x;
    for (int i = blockIdx.x * blockDim.x + threadIdx.x; i < NVEC; i += stride) {
        float4 a0 = A0[i], a1 = A1[i], a2 = A2[i];
        float4 r0, r1, r2;
#define LANE(c)                                                \
        r0.c = x00 * a0.c + x01 * a1.c + x02 * a2.c + o0;      \
        r1.c = x10 * a0.c + x11 * a1.c + x12 * a2.c + o1;      \
        r2.c = x20 * a0.c + x21 * a1.c + x22 * a2.c + o2;
        LANE(x) LANE(y) LANE(z) LANE(w)
#undef LANE
        O0[i] = r0; O1[i] = r1; O2[i] = r2;
    }
}

extern "C" void kernel_launch(void* const* d_in, const int* in_sizes, int n_in,
                              void* d_out, int out_size) {
    const float* src = (const float*)d_in[0];
    const float* dst = (const float*)d_in[1];
    float* out = (float*)d_out;

    zero_acc_kernel<<<2, 256>>>();

    dim3 rgrid(128, BATCH);
    reduce_kernel<<<rgrid, 256>>>(src, dst);

    solve_kernel<<<1, 32>>>();

    dim3 agrid(128, BATCH);
    apply_kernel<<<agrid, 256>>>(src, out);
}